// round 5
// baseline (speedup 1.0000x reference)
#include <cuda_runtime.h>
#include <cuda_bf16.h>

// Problem constants (GatedMessageGcn_3126736191774)
#define RR   1000          // number of relations
#define DD   100           // feature dim
#define MM   2000000       // num_messages (segments)
#define EMAX 16000000      // edges

// ---------------------------------------------------------------------------
// Device scratch (static; no runtime allocation allowed)
// ---------------------------------------------------------------------------
__device__ float g_table[RR * RR];   // sigmoid(Gs @ Gr^T), 4 MB (L2-resident)
__device__ float g_denom[MM];        // segment sums, 8 MB   (L2-resident)
__device__ int   g_recv[EMAX];       // compacted receiver idx, 64 MB

// ---------------------------------------------------------------------------
// Kernel 1 (fused): blocks [0, 1024) compute the 32x32-tiled GEMM + sigmoid;
//                   blocks [1024, ...) zero the denom buffer (float4).
// ---------------------------------------------------------------------------
#define KPAD 101
#define GEMM_BLOCKS 1024          // 32 x 32 tiles of 32x32 covering 1000x1000
#define ZERO_BLOCKS ((MM / 4 + 255) / 256)

__global__ void gemm_sigmoid_zero_kernel(const float* __restrict__ Gs,
                                         const float* __restrict__ Gr) {
    __shared__ float As[32 * KPAD];
    __shared__ float Bs[32 * KPAD];

    const int b = blockIdx.x;
    const int tid = threadIdx.x;

    if (b >= GEMM_BLOCKS) {
        // denom zeroing part
        int i = (b - GEMM_BLOCKS) * 256 + tid;
        if (i < MM / 4)
            reinterpret_cast<float4*>(g_denom)[i] = make_float4(0, 0, 0, 0);
        return;
    }

    const int i0 = (b >> 5) * 32;   // tile row
    const int j0 = (b & 31) * 32;   // tile col

    for (int idx = tid; idx < 32 * DD; idx += 256) {
        int row = idx / DD;
        int k   = idx % DD;
        int gi = i0 + row;
        int gj = j0 + row;
        As[row * KPAD + k] = (gi < RR) ? Gs[gi * DD + k] : 0.0f;
        Bs[row * KPAD + k] = (gj < RR) ? Gr[gj * DD + k] : 0.0f;
    }
    __syncthreads();

    const int tx = tid & 31;
    const int ty = tid >> 5;

    float acc0 = 0.f, acc1 = 0.f, acc2 = 0.f, acc3 = 0.f;

    #pragma unroll 4
    for (int k = 0; k < DD; k++) {
        float bv = Bs[tx * KPAD + k];
        acc0 += As[(ty     ) * KPAD + k] * bv;
        acc1 += As[(ty +  8) * KPAD + k] * bv;
        acc2 += As[(ty + 16) * KPAD + k] * bv;
        acc3 += As[(ty + 24) * KPAD + k] * bv;
    }

    const int j = j0 + tx;
    if (j < RR) {
        int i;
        i = i0 + ty;      if (i < RR) g_table[i * RR + j] = 1.0f / (1.0f + __expf(-acc0));
        i = i0 + ty + 8;  if (i < RR) g_table[i * RR + j] = 1.0f / (1.0f + __expf(-acc1));
        i = i0 + ty + 16; if (i < RR) g_table[i * RR + j] = 1.0f / (1.0f + __expf(-acc2));
        i = i0 + ty + 24; if (i < RR) g_table[i * RR + j] = 1.0f / (1.0f + __expf(-acc3));
    }
}

// ---------------------------------------------------------------------------
// Kernel 2 (pass 1): 8 edges/thread.
//   Streaming index reads use __ldcs (evict-first) to preserve L2 for the
//   gates/recv writes that pass 2 re-reads. 8 independent table gathers,
//   8 REDG atomics into denom.
// ---------------------------------------------------------------------------
__global__ void edge_pass1_kernel(const int4* __restrict__ rel4,
                                  const int4* __restrict__ msg4,
                                  float4* __restrict__ gates4,
                                  int E8) {
    int t = blockIdx.x * blockDim.x + threadIdx.x;
    if (t >= E8) return;

    // 4x int4 = 8 (s,r) pairs; evict-first streaming loads
    int4 ra = __ldcs(&rel4[4 * t]);
    int4 rb = __ldcs(&rel4[4 * t + 1]);
    int4 rc = __ldcs(&rel4[4 * t + 2]);
    int4 rd = __ldcs(&rel4[4 * t + 3]);
    int4 ma = __ldcs(&msg4[4 * t]);
    int4 mb = __ldcs(&msg4[4 * t + 1]);
    int4 mc = __ldcs(&msg4[4 * t + 2]);
    int4 md = __ldcs(&msg4[4 * t + 3]);

    // 8 independent L2 gathers into the 4 MB gate table
    float g0 = __ldg(&g_table[ra.x * RR + ra.y]);
    float g1 = __ldg(&g_table[ra.z * RR + ra.w]);
    float g2 = __ldg(&g_table[rb.x * RR + rb.y]);
    float g3 = __ldg(&g_table[rb.z * RR + rb.w]);
    float g4 = __ldg(&g_table[rc.x * RR + rc.y]);
    float g5 = __ldg(&g_table[rc.z * RR + rc.w]);
    float g6 = __ldg(&g_table[rd.x * RR + rd.y]);
    float g7 = __ldg(&g_table[rd.z * RR + rd.w]);

    gates4[2 * t]     = make_float4(g0, g1, g2, g3);
    gates4[2 * t + 1] = make_float4(g4, g5, g6, g7);
    reinterpret_cast<int4*>(g_recv)[2 * t]     = make_int4(ma.y, ma.w, mb.y, mb.w);
    reinterpret_cast<int4*>(g_recv)[2 * t + 1] = make_int4(mc.y, mc.w, md.y, md.w);

    atomicAdd(&g_denom[ma.y], g0);   // return value unused -> REDG
    atomicAdd(&g_denom[ma.w], g1);
    atomicAdd(&g_denom[mb.y], g2);
    atomicAdd(&g_denom[mb.w], g3);
    atomicAdd(&g_denom[mc.y], g4);
    atomicAdd(&g_denom[mc.w], g5);
    atomicAdd(&g_denom[md.y], g6);
    atomicAdd(&g_denom[md.w], g7);
}

// ---------------------------------------------------------------------------
// Kernel 3 (pass 2): weights = gate / (denom[recv] + 1e-8), 8 edges/thread
// ---------------------------------------------------------------------------
__global__ void edge_pass2_kernel(float4* __restrict__ out4, int E8) {
    int t = blockIdx.x * blockDim.x + threadIdx.x;
    if (t >= E8) return;

    const int4* recv4 = reinterpret_cast<const int4*>(g_recv);
    int4 r0 = __ldcs(&recv4[2 * t]);
    int4 r1 = __ldcs(&recv4[2 * t + 1]);
    float4 ga = __ldcs(&out4[2 * t]);
    float4 gb = __ldcs(&out4[2 * t + 1]);

    // 8 independent L2 gathers into the 8 MB denom table
    float d0 = __ldg(&g_denom[r0.x]);
    float d1 = __ldg(&g_denom[r0.y]);
    float d2 = __ldg(&g_denom[r0.z]);
    float d3 = __ldg(&g_denom[r0.w]);
    float d4 = __ldg(&g_denom[r1.x]);
    float d5 = __ldg(&g_denom[r1.y]);
    float d6 = __ldg(&g_denom[r1.z]);
    float d7 = __ldg(&g_denom[r1.w]);

    float4 oa = make_float4(ga.x / (d0 + 1e-8f), ga.y / (d1 + 1e-8f),
                            ga.z / (d2 + 1e-8f), ga.w / (d3 + 1e-8f));
    float4 ob = make_float4(gb.x / (d4 + 1e-8f), gb.y / (d5 + 1e-8f),
                            gb.z / (d6 + 1e-8f), gb.w / (d7 + 1e-8f));
    __stcs(&out4[2 * t],     oa);
    __stcs(&out4[2 * t + 1], ob);
}

// ---------------------------------------------------------------------------
// Scalar tails (E % 8 != 0 safety; E=16M so normally empty)
// ---------------------------------------------------------------------------
__global__ void edge_tail_kernel(const int2* __restrict__ rel,
                                 const int2* __restrict__ msg,
                                 float* __restrict__ gates,
                                 int start, int E) {
    int e = start + blockIdx.x * blockDim.x + threadIdx.x;
    if (e >= E) return;
    int2 rp = rel[e];
    int  rv = msg[e].y;
    float g = __ldg(&g_table[rp.x * RR + rp.y]);
    gates[e] = g;
    g_recv[e] = rv;
    atomicAdd(&g_denom[rv], g);
}

__global__ void edge_tail2_kernel(float* __restrict__ out,
                                  int start, int E) {
    int e = start + blockIdx.x * blockDim.x + threadIdx.x;
    if (e >= E) return;
    out[e] = out[e] / (__ldg(&g_denom[g_recv[e]]) + 1e-8f);
}

// ---------------------------------------------------------------------------
// Launch
// ---------------------------------------------------------------------------
extern "C" void kernel_launch(void* const* d_in, const int* in_sizes, int n_in,
                              void* d_out, int out_size) {
    const float* Gs = (const float*)d_in[0];
    const float* Gr = (const float*)d_in[1];
    const int4*  rel4 = (const int4*)d_in[2];
    const int4*  msg4 = (const int4*)d_in[3];
    float* out = (float*)d_out;

    int E  = in_sizes[2] / 2;   // (E,2) index pairs
    int E8 = E / 8;
    int tail = E - E8 * 8;

    // 1. gate table + denom zeroing (fused)
    gemm_sigmoid_zero_kernel<<<GEMM_BLOCKS + ZERO_BLOCKS, 256>>>(Gs, Gr);

    // 2. pass 1: gates + segment sum
    int nblk = (E8 + 255) / 256;
    edge_pass1_kernel<<<nblk, 256>>>(rel4, msg4, (float4*)out, E8);
    if (tail) {
        edge_tail_kernel<<<1, 256>>>((const int2*)d_in[2], (const int2*)d_in[3],
                                     out, E8 * 8, E);
    }

    // 3. pass 2: normalize
    edge_pass2_kernel<<<nblk, 256>>>((float4*)out, E8);
    if (tail) {
        edge_tail2_kernel<<<1, 256>>>(out, E8 * 8, E);
    }
}

// round 6
// speedup vs baseline: 1.0012x; 1.0012x over previous
#include <cuda_runtime.h>
#include <cuda_bf16.h>

// Problem constants (GatedMessageGcn_3126736191774)
#define RR   1000          // number of relations
#define DD   100           // feature dim
#define MM   2000000       // num_messages (segments)
#define EMAX 16000000      // edges

// ---------------------------------------------------------------------------
// Device scratch (static; no runtime allocation allowed)
// ---------------------------------------------------------------------------
__device__ float g_table[RR * RR];   // sigmoid(Gs @ Gr^T), 4 MB (L2-resident)
__device__ float g_denom[MM];        // segment sums, 8 MB   (L2-resident)
__device__ int   g_recv[EMAX];       // compacted receiver idx, 64 MB

// ---------------------------------------------------------------------------
// Kernel 1: 32x32-tiled GEMM (K=100) + sigmoid epilogue  (R4-proven)
// ---------------------------------------------------------------------------
#define KPAD 101

__global__ void gemm_sigmoid_kernel(const float* __restrict__ Gs,
                                    const float* __restrict__ Gr) {
    __shared__ float As[32 * KPAD];
    __shared__ float Bs[32 * KPAD];

    const int tid = threadIdx.x;
    const int i0 = blockIdx.y * 32;
    const int j0 = blockIdx.x * 32;

    for (int idx = tid; idx < 32 * DD; idx += 256) {
        int row = idx / DD;
        int k   = idx % DD;
        int gi = i0 + row;
        int gj = j0 + row;
        As[row * KPAD + k] = (gi < RR) ? Gs[gi * DD + k] : 0.0f;
        Bs[row * KPAD + k] = (gj < RR) ? Gr[gj * DD + k] : 0.0f;
    }
    __syncthreads();

    const int tx = tid & 31;
    const int ty = tid >> 5;

    float acc0 = 0.f, acc1 = 0.f, acc2 = 0.f, acc3 = 0.f;

    #pragma unroll 4
    for (int k = 0; k < DD; k++) {
        float b = Bs[tx * KPAD + k];
        acc0 += As[(ty     ) * KPAD + k] * b;
        acc1 += As[(ty +  8) * KPAD + k] * b;
        acc2 += As[(ty + 16) * KPAD + k] * b;
        acc3 += As[(ty + 24) * KPAD + k] * b;
    }

    const int j = j0 + tx;
    if (j < RR) {
        int i;
        i = i0 + ty;      if (i < RR) g_table[i * RR + j] = 1.0f / (1.0f + __expf(-acc0));
        i = i0 + ty + 8;  if (i < RR) g_table[i * RR + j] = 1.0f / (1.0f + __expf(-acc1));
        i = i0 + ty + 16; if (i < RR) g_table[i * RR + j] = 1.0f / (1.0f + __expf(-acc2));
        i = i0 + ty + 24; if (i < RR) g_table[i * RR + j] = 1.0f / (1.0f + __expf(-acc3));
    }
}

// ---------------------------------------------------------------------------
// Kernel 2: zero the segment-sum buffer (vectorized; MM % 4 == 0)
// ---------------------------------------------------------------------------
__global__ void zero_denom_kernel() {
    int i = blockIdx.x * blockDim.x + threadIdx.x;
    if (i < MM / 4) reinterpret_cast<float4*>(g_denom)[i] = make_float4(0, 0, 0, 0);
}

// ---------------------------------------------------------------------------
// Kernel 3 (pass 1): 8 edges/thread, plain loads (no cache hints).
//   8 independent table gathers (MLP), stores gates (2x float4) + recv
//   (2x int4), 8 REDG atomics into denom.
// ---------------------------------------------------------------------------
__global__ void edge_pass1_kernel(const int4* __restrict__ rel4,
                                  const int4* __restrict__ msg4,
                                  float4* __restrict__ gates4,
                                  int E8) {
    int t = blockIdx.x * blockDim.x + threadIdx.x;
    if (t >= E8) return;

    int4 ra = rel4[4 * t];
    int4 rb = rel4[4 * t + 1];
    int4 rc = rel4[4 * t + 2];
    int4 rd = rel4[4 * t + 3];
    int4 ma = msg4[4 * t];
    int4 mb = msg4[4 * t + 1];
    int4 mc = msg4[4 * t + 2];
    int4 md = msg4[4 * t + 3];

    // 8 independent L2 gathers into the 4 MB gate table
    float g0 = __ldg(&g_table[ra.x * RR + ra.y]);
    float g1 = __ldg(&g_table[ra.z * RR + ra.w]);
    float g2 = __ldg(&g_table[rb.x * RR + rb.y]);
    float g3 = __ldg(&g_table[rb.z * RR + rb.w]);
    float g4 = __ldg(&g_table[rc.x * RR + rc.y]);
    float g5 = __ldg(&g_table[rc.z * RR + rc.w]);
    float g6 = __ldg(&g_table[rd.x * RR + rd.y]);
    float g7 = __ldg(&g_table[rd.z * RR + rd.w]);

    gates4[2 * t]     = make_float4(g0, g1, g2, g3);
    gates4[2 * t + 1] = make_float4(g4, g5, g6, g7);
    reinterpret_cast<int4*>(g_recv)[2 * t]     = make_int4(ma.y, ma.w, mb.y, mb.w);
    reinterpret_cast<int4*>(g_recv)[2 * t + 1] = make_int4(mc.y, mc.w, md.y, md.w);

    atomicAdd(&g_denom[ma.y], g0);   // return value unused -> REDG
    atomicAdd(&g_denom[ma.w], g1);
    atomicAdd(&g_denom[mb.y], g2);
    atomicAdd(&g_denom[mb.w], g3);
    atomicAdd(&g_denom[mc.y], g4);
    atomicAdd(&g_denom[mc.w], g5);
    atomicAdd(&g_denom[md.y], g6);
    atomicAdd(&g_denom[md.w], g7);
}

// ---------------------------------------------------------------------------
// Kernel 4 (pass 2): weights = gate / (denom[recv] + 1e-8), 8 edges/thread
// ---------------------------------------------------------------------------
__global__ void edge_pass2_kernel(float4* __restrict__ out4, int E8) {
    int t = blockIdx.x * blockDim.x + threadIdx.x;
    if (t >= E8) return;

    const int4* recv4 = reinterpret_cast<const int4*>(g_recv);
    int4 r0 = recv4[2 * t];
    int4 r1 = recv4[2 * t + 1];
    float4 ga = out4[2 * t];
    float4 gb = out4[2 * t + 1];

    // 8 independent L2 gathers into the 8 MB denom table
    float d0 = __ldg(&g_denom[r0.x]);
    float d1 = __ldg(&g_denom[r0.y]);
    float d2 = __ldg(&g_denom[r0.z]);
    float d3 = __ldg(&g_denom[r0.w]);
    float d4 = __ldg(&g_denom[r1.x]);
    float d5 = __ldg(&g_denom[r1.y]);
    float d6 = __ldg(&g_denom[r1.z]);
    float d7 = __ldg(&g_denom[r1.w]);

    out4[2 * t]     = make_float4(ga.x / (d0 + 1e-8f), ga.y / (d1 + 1e-8f),
                                  ga.z / (d2 + 1e-8f), ga.w / (d3 + 1e-8f));
    out4[2 * t + 1] = make_float4(gb.x / (d4 + 1e-8f), gb.y / (d5 + 1e-8f),
                                  gb.z / (d6 + 1e-8f), gb.w / (d7 + 1e-8f));
}

// ---------------------------------------------------------------------------
// Scalar tails (E % 8 != 0 safety; E=16M so normally empty)
// ---------------------------------------------------------------------------
__global__ void edge_tail_kernel(const int2* __restrict__ rel,
                                 const int2* __restrict__ msg,
                                 float* __restrict__ gates,
                                 int start, int E) {
    int e = start + blockIdx.x * blockDim.x + threadIdx.x;
    if (e >= E) return;
    int2 rp = rel[e];
    int  rv = msg[e].y;
    float g = __ldg(&g_table[rp.x * RR + rp.y]);
    gates[e] = g;
    g_recv[e] = rv;
    atomicAdd(&g_denom[rv], g);
}

__global__ void edge_tail2_kernel(float* __restrict__ out,
                                  int start, int E) {
    int e = start + blockIdx.x * blockDim.x + threadIdx.x;
    if (e >= E) return;
    out[e] = out[e] / (__ldg(&g_denom[g_recv[e]]) + 1e-8f);
}

// ---------------------------------------------------------------------------
// Launch
// ---------------------------------------------------------------------------
extern "C" void kernel_launch(void* const* d_in, const int* in_sizes, int n_in,
                              void* d_out, int out_size) {
    const float* Gs = (const float*)d_in[0];
    const float* Gr = (const float*)d_in[1];
    const int4*  rel4 = (const int4*)d_in[2];
    const int4*  msg4 = (const int4*)d_in[3];
    float* out = (float*)d_out;

    int E  = in_sizes[2] / 2;   // (E,2) index pairs
    int E8 = E / 8;
    int tail = E - E8 * 8;

    // 1. gate table
    dim3 ggrid((RR + 31) / 32, (RR + 31) / 32);
    gemm_sigmoid_kernel<<<ggrid, 256>>>(Gs, Gr);

    // 2. zero denom
    zero_denom_kernel<<<(MM / 4 + 255) / 256, 256>>>();

    // 3. pass 1: gates + segment sum
    int nblk = (E8 + 255) / 256;
    edge_pass1_kernel<<<nblk, 256>>>(rel4, msg4, (float4*)out, E8);
    if (tail) {
        edge_tail_kernel<<<1, 256>>>((const int2*)d_in[2], (const int2*)d_in[3],
                                     out, E8 * 8, E);
    }

    // 4. pass 2: normalize
    edge_pass2_kernel<<<nblk, 256>>>((float4*)out, E8);
    if (tail) {
        edge_tail2_kernel<<<1, 256>>>(out, E8 * 8, E);
    }
}

// round 7
// speedup vs baseline: 1.1471x; 1.1458x over previous
#include <cuda_runtime.h>
#include <cuda_bf16.h>

// Problem constants (GatedMessageGcn_3126736191774)
#define RR   1000          // number of relations
#define DD   100           // feature dim
#define MM   2000000       // num_messages (segments)
#define EMAX 16000000      // edges

// ---------------------------------------------------------------------------
// Device scratch (static; no runtime allocation allowed)
// ---------------------------------------------------------------------------
__device__ float g_table[RR * RR];   // sigmoid(Gs @ Gr^T), 4 MB (L2-resident)
__device__ float g_denom[MM];        // segment sums, 8 MB   (L2-resident)
__device__ int   g_recv[EMAX];       // compacted receiver idx, 64 MB

// ---------------------------------------------------------------------------
// Kernel 1: 32x32-tiled GEMM (K=100) + sigmoid epilogue  (R4-proven)
// ---------------------------------------------------------------------------
#define KPAD 101

__global__ void gemm_sigmoid_kernel(const float* __restrict__ Gs,
                                    const float* __restrict__ Gr) {
    __shared__ float As[32 * KPAD];
    __shared__ float Bs[32 * KPAD];

    const int tid = threadIdx.x;
    const int i0 = blockIdx.y * 32;
    const int j0 = blockIdx.x * 32;

    for (int idx = tid; idx < 32 * DD; idx += 256) {
        int row = idx / DD;
        int k   = idx % DD;
        int gi = i0 + row;
        int gj = j0 + row;
        As[row * KPAD + k] = (gi < RR) ? Gs[gi * DD + k] : 0.0f;
        Bs[row * KPAD + k] = (gj < RR) ? Gr[gj * DD + k] : 0.0f;
    }
    __syncthreads();

    const int tx = tid & 31;
    const int ty = tid >> 5;

    float acc0 = 0.f, acc1 = 0.f, acc2 = 0.f, acc3 = 0.f;

    #pragma unroll 4
    for (int k = 0; k < DD; k++) {
        float b = Bs[tx * KPAD + k];
        acc0 += As[(ty     ) * KPAD + k] * b;
        acc1 += As[(ty +  8) * KPAD + k] * b;
        acc2 += As[(ty + 16) * KPAD + k] * b;
        acc3 += As[(ty + 24) * KPAD + k] * b;
    }

    const int j = j0 + tx;
    if (j < RR) {
        int i;
        i = i0 + ty;      if (i < RR) g_table[i * RR + j] = 1.0f / (1.0f + __expf(-acc0));
        i = i0 + ty + 8;  if (i < RR) g_table[i * RR + j] = 1.0f / (1.0f + __expf(-acc1));
        i = i0 + ty + 16; if (i < RR) g_table[i * RR + j] = 1.0f / (1.0f + __expf(-acc2));
        i = i0 + ty + 24; if (i < RR) g_table[i * RR + j] = 1.0f / (1.0f + __expf(-acc3));
    }
}

// ---------------------------------------------------------------------------
// Kernel 2: zero the segment-sum buffer (vectorized; MM % 4 == 0)
// ---------------------------------------------------------------------------
__global__ void zero_denom_kernel() {
    int i = blockIdx.x * blockDim.x + threadIdx.x;
    if (i < MM / 4) reinterpret_cast<float4*>(g_denom)[i] = make_float4(0, 0, 0, 0);
}

// ---------------------------------------------------------------------------
// Kernel 3 (pass 1): 4 edges/iter, grid-stride, one-iter-ahead prefetch of
//   the streaming index loads. Gather batch = 4/thread (128 lines/warp,
//   under the 248-entry L1tex queue).
// ---------------------------------------------------------------------------
__global__ void edge_pass1_kernel(const int4* __restrict__ rel4,
                                  const int4* __restrict__ msg4,
                                  float4* __restrict__ gates4,
                                  int E4, int stride) {
    int t = blockIdx.x * blockDim.x + threadIdx.x;
    if (t >= E4) return;

    int4 ra = rel4[2 * t];
    int4 rb = rel4[2 * t + 1];
    int4 ma = msg4[2 * t];
    int4 mb = msg4[2 * t + 1];

    while (true) {
        // prefetch next chunk's streams before consuming current gathers
        int tn = t + stride;
        bool more = tn < E4;
        int4 ra2, rb2, ma2, mb2;
        if (more) {
            ra2 = rel4[2 * tn];
            rb2 = rel4[2 * tn + 1];
            ma2 = msg4[2 * tn];
            mb2 = msg4[2 * tn + 1];
        }

        // 4 independent L2 gathers
        float g0 = __ldg(&g_table[ra.x * RR + ra.y]);
        float g1 = __ldg(&g_table[ra.z * RR + ra.w]);
        float g2 = __ldg(&g_table[rb.x * RR + rb.y]);
        float g3 = __ldg(&g_table[rb.z * RR + rb.w]);

        gates4[t] = make_float4(g0, g1, g2, g3);
        reinterpret_cast<int4*>(g_recv)[t] = make_int4(ma.y, ma.w, mb.y, mb.w);

        atomicAdd(&g_denom[ma.y], g0);   // return unused -> REDG
        atomicAdd(&g_denom[ma.w], g1);
        atomicAdd(&g_denom[mb.y], g2);
        atomicAdd(&g_denom[mb.w], g3);

        if (!more) break;
        t = tn; ra = ra2; rb = rb2; ma = ma2; mb = mb2;
    }
}

// ---------------------------------------------------------------------------
// Kernel 4 (pass 2): weights = gate / (denom[recv] + 1e-8), 4 edges/iter,
//   grid-stride with one-iter-ahead stream prefetch.
// ---------------------------------------------------------------------------
__global__ void edge_pass2_kernel(float4* __restrict__ out4, int E4, int stride) {
    int t = blockIdx.x * blockDim.x + threadIdx.x;
    if (t >= E4) return;

    const int4* recv4 = reinterpret_cast<const int4*>(g_recv);
    int4   r = recv4[t];
    float4 g = out4[t];

    while (true) {
        int tn = t + stride;
        bool more = tn < E4;
        int4 rn; float4 gn;
        if (more) {           // prefetch next streams (issued before store)
            rn = recv4[tn];
            gn = out4[tn];
        }

        float d0 = __ldg(&g_denom[r.x]);
        float d1 = __ldg(&g_denom[r.y]);
        float d2 = __ldg(&g_denom[r.z]);
        float d3 = __ldg(&g_denom[r.w]);

        out4[t] = make_float4(g.x / (d0 + 1e-8f), g.y / (d1 + 1e-8f),
                              g.z / (d2 + 1e-8f), g.w / (d3 + 1e-8f));

        if (!more) break;
        t = tn; r = rn; g = gn;
    }
}

// ---------------------------------------------------------------------------
// Scalar tails (E % 4 != 0 safety; E=16M so normally empty)
// ---------------------------------------------------------------------------
__global__ void edge_tail_kernel(const int2* __restrict__ rel,
                                 const int2* __restrict__ msg,
                                 float* __restrict__ gates,
                                 int start, int E) {
    int e = start + blockIdx.x * blockDim.x + threadIdx.x;
    if (e >= E) return;
    int2 rp = rel[e];
    int  rv = msg[e].y;
    float g = __ldg(&g_table[rp.x * RR + rp.y]);
    gates[e] = g;
    g_recv[e] = rv;
    atomicAdd(&g_denom[rv], g);
}

__global__ void edge_tail2_kernel(float* __restrict__ out,
                                  int start, int E) {
    int e = start + blockIdx.x * blockDim.x + threadIdx.x;
    if (e >= E) return;
    out[e] = out[e] / (__ldg(&g_denom[g_recv[e]]) + 1e-8f);
}

// ---------------------------------------------------------------------------
// Launch
// ---------------------------------------------------------------------------
extern "C" void kernel_launch(void* const* d_in, const int* in_sizes, int n_in,
                              void* d_out, int out_size) {
    const float* Gs = (const float*)d_in[0];
    const float* Gr = (const float*)d_in[1];
    const int4*  rel4 = (const int4*)d_in[2];
    const int4*  msg4 = (const int4*)d_in[3];
    float* out = (float*)d_out;

    int E  = in_sizes[2] / 2;   // (E,2) index pairs
    int E4 = E / 4;
    int tail = E - E4 * 4;

    // 1. gate table
    dim3 ggrid((RR + 31) / 32, (RR + 31) / 32);
    gemm_sigmoid_kernel<<<ggrid, 256>>>(Gs, Gr);

    // 2. zero denom
    zero_denom_kernel<<<(MM / 4 + 255) / 256, 256>>>();

    // 3. pass 1: gates + segment sum (grid-stride, ~8 iters/thread)
    int nblk = (E4 + 255) / 256;
    if (nblk > 2048) nblk = 2048;
    int stride = nblk * 256;
    edge_pass1_kernel<<<nblk, 256>>>(rel4, msg4, (float4*)out, E4, stride);
    if (tail) {
        edge_tail_kernel<<<1, 256>>>((const int2*)d_in[2], (const int2*)d_in[3],
                                     out, E4 * 4, E);
    }

    // 4. pass 2: normalize
    edge_pass2_kernel<<<nblk, 256>>>((float4*)out, E4, stride);
    if (tail) {
        edge_tail2_kernel<<<1, 256>>>(out, E4 * 4, E);
    }
}

// round 8
// speedup vs baseline: 1.1687x; 1.0188x over previous
#include <cuda_runtime.h>
#include <cuda_bf16.h>

// Problem constants (GatedMessageGcn_3126736191774)
#define RR   1000          // number of relations
#define DD   100           // feature dim
#define MM   2000000       // num_messages (segments)
#define EMAX 16000000      // edges

// ---------------------------------------------------------------------------
// Device scratch (static; no runtime allocation allowed)
// ---------------------------------------------------------------------------
__device__ float g_table[RR * RR];   // sigmoid(Gs @ Gr^T), 4 MB (L2-resident)
__device__ float g_denom[MM];        // segment sums, 8 MB   (L2-resident)
__device__ int   g_recv[EMAX];       // compacted receiver idx, 64 MB

// ---------------------------------------------------------------------------
// Kernel 1: 32x32-tiled GEMM (K=100) + sigmoid epilogue  (R4-proven)
// ---------------------------------------------------------------------------
#define KPAD 101

__global__ void gemm_sigmoid_kernel(const float* __restrict__ Gs,
                                    const float* __restrict__ Gr) {
    __shared__ float As[32 * KPAD];
    __shared__ float Bs[32 * KPAD];

    const int tid = threadIdx.x;
    const int i0 = blockIdx.y * 32;
    const int j0 = blockIdx.x * 32;

    for (int idx = tid; idx < 32 * DD; idx += 256) {
        int row = idx / DD;
        int k   = idx % DD;
        int gi = i0 + row;
        int gj = j0 + row;
        As[row * KPAD + k] = (gi < RR) ? Gs[gi * DD + k] : 0.0f;
        Bs[row * KPAD + k] = (gj < RR) ? Gr[gj * DD + k] : 0.0f;
    }
    __syncthreads();

    const int tx = tid & 31;
    const int ty = tid >> 5;

    float acc0 = 0.f, acc1 = 0.f, acc2 = 0.f, acc3 = 0.f;

    #pragma unroll 4
    for (int k = 0; k < DD; k++) {
        float b = Bs[tx * KPAD + k];
        acc0 += As[(ty     ) * KPAD + k] * b;
        acc1 += As[(ty +  8) * KPAD + k] * b;
        acc2 += As[(ty + 16) * KPAD + k] * b;
        acc3 += As[(ty + 24) * KPAD + k] * b;
    }

    const int j = j0 + tx;
    if (j < RR) {
        int i;
        i = i0 + ty;      if (i < RR) g_table[i * RR + j] = 1.0f / (1.0f + __expf(-acc0));
        i = i0 + ty + 8;  if (i < RR) g_table[i * RR + j] = 1.0f / (1.0f + __expf(-acc1));
        i = i0 + ty + 16; if (i < RR) g_table[i * RR + j] = 1.0f / (1.0f + __expf(-acc2));
        i = i0 + ty + 24; if (i < RR) g_table[i * RR + j] = 1.0f / (1.0f + __expf(-acc3));
    }
}

// ---------------------------------------------------------------------------
// Kernel 2 (pass 1): 8 edges/thread as TWO strided coalesced chunks.
//   Thread t handles chunk t and chunk t+S, so every stream load/store
//   instruction stays warp-contiguous (4 lines/instr) while the thread
//   carries 8 independent scattered gathers + 8 REDG atomics.
// ---------------------------------------------------------------------------
__global__ void edge_pass1_kernel(const int4* __restrict__ rel4,
                                  const int4* __restrict__ msg4,
                                  float4* __restrict__ gates4,
                                  int E4, int S) {
    int t = blockIdx.x * blockDim.x + threadIdx.x;
    if (t >= S) return;
    int u = t + S;
    bool two = (u < E4);

    // chunk A streams (coalesced)
    int4 ra = rel4[2 * t];
    int4 rb = rel4[2 * t + 1];
    int4 ma = msg4[2 * t];
    int4 mb = msg4[2 * t + 1];
    // chunk B streams (coalesced)
    int4 rc, rd, mc, md;
    if (two) {
        rc = rel4[2 * u];
        rd = rel4[2 * u + 1];
        mc = msg4[2 * u];
        md = msg4[2 * u + 1];
    }

    // 8 independent L2 gathers into the 4 MB gate table
    float g0 = __ldg(&g_table[ra.x * RR + ra.y]);
    float g1 = __ldg(&g_table[ra.z * RR + ra.w]);
    float g2 = __ldg(&g_table[rb.x * RR + rb.y]);
    float g3 = __ldg(&g_table[rb.z * RR + rb.w]);
    float g4 = 0.f, g5 = 0.f, g6 = 0.f, g7 = 0.f;
    if (two) {
        g4 = __ldg(&g_table[rc.x * RR + rc.y]);
        g5 = __ldg(&g_table[rc.z * RR + rc.w]);
        g6 = __ldg(&g_table[rd.x * RR + rd.y]);
        g7 = __ldg(&g_table[rd.z * RR + rd.w]);
    }

    // coalesced stores (one float4 / int4 per chunk index)
    gates4[t] = make_float4(g0, g1, g2, g3);
    reinterpret_cast<int4*>(g_recv)[t] = make_int4(ma.y, ma.w, mb.y, mb.w);
    if (two) {
        gates4[u] = make_float4(g4, g5, g6, g7);
        reinterpret_cast<int4*>(g_recv)[u] = make_int4(mc.y, mc.w, md.y, md.w);
    }

    atomicAdd(&g_denom[ma.y], g0);   // return unused -> REDG
    atomicAdd(&g_denom[ma.w], g1);
    atomicAdd(&g_denom[mb.y], g2);
    atomicAdd(&g_denom[mb.w], g3);
    if (two) {
        atomicAdd(&g_denom[mc.y], g4);
        atomicAdd(&g_denom[mc.w], g5);
        atomicAdd(&g_denom[md.y], g6);
        atomicAdd(&g_denom[md.w], g7);
    }
}

// ---------------------------------------------------------------------------
// Kernel 3 (pass 2): weights = gate / (denom[recv] + 1e-8)
//   Same two-strided-chunk structure: 8 gathers/thread, ideal coalescing.
// ---------------------------------------------------------------------------
__global__ void edge_pass2_kernel(float4* __restrict__ out4, int E4, int S) {
    int t = blockIdx.x * blockDim.x + threadIdx.x;
    if (t >= S) return;
    int u = t + S;
    bool two = (u < E4);

    const int4* recv4 = reinterpret_cast<const int4*>(g_recv);
    int4   r0 = recv4[t];
    float4 ga = out4[t];
    int4   r1;
    float4 gb;
    if (two) {
        r1 = recv4[u];
        gb = out4[u];
    }

    float d0 = __ldg(&g_denom[r0.x]);
    float d1 = __ldg(&g_denom[r0.y]);
    float d2 = __ldg(&g_denom[r0.z]);
    float d3 = __ldg(&g_denom[r0.w]);
    float d4 = 1.f, d5 = 1.f, d6 = 1.f, d7 = 1.f;
    if (two) {
        d4 = __ldg(&g_denom[r1.x]);
        d5 = __ldg(&g_denom[r1.y]);
        d6 = __ldg(&g_denom[r1.z]);
        d7 = __ldg(&g_denom[r1.w]);
    }

    out4[t] = make_float4(ga.x / (d0 + 1e-8f), ga.y / (d1 + 1e-8f),
                          ga.z / (d2 + 1e-8f), ga.w / (d3 + 1e-8f));
    if (two) {
        out4[u] = make_float4(gb.x / (d4 + 1e-8f), gb.y / (d5 + 1e-8f),
                              gb.z / (d6 + 1e-8f), gb.w / (d7 + 1e-8f));
    }
}

// ---------------------------------------------------------------------------
// Scalar tails (E % 4 != 0 safety; E=16M so normally empty)
// ---------------------------------------------------------------------------
__global__ void edge_tail_kernel(const int2* __restrict__ rel,
                                 const int2* __restrict__ msg,
                                 float* __restrict__ gates,
                                 int start, int E) {
    int e = start + blockIdx.x * blockDim.x + threadIdx.x;
    if (e >= E) return;
    int2 rp = rel[e];
    int  rv = msg[e].y;
    float g = __ldg(&g_table[rp.x * RR + rp.y]);
    gates[e] = g;
    g_recv[e] = rv;
    atomicAdd(&g_denom[rv], g);
}

__global__ void edge_tail2_kernel(float* __restrict__ out,
                                  int start, int E) {
    int e = start + blockIdx.x * blockDim.x + threadIdx.x;
    if (e >= E) return;
    out[e] = out[e] / (__ldg(&g_denom[g_recv[e]]) + 1e-8f);
}

// ---------------------------------------------------------------------------
// Host helper: cached symbol address for memset (defined BEFORE use)
// ---------------------------------------------------------------------------
static void* denom_device_addr() {
    static void* p = nullptr;
    if (!p) cudaGetSymbolAddress(&p, g_denom);
    return p;
}

// ---------------------------------------------------------------------------
// Launch
// ---------------------------------------------------------------------------
extern "C" void kernel_launch(void* const* d_in, const int* in_sizes, int n_in,
                              void* d_out, int out_size) {
    const float* Gs = (const float*)d_in[0];
    const float* Gr = (const float*)d_in[1];
    const int4*  rel4 = (const int4*)d_in[2];
    const int4*  msg4 = (const int4*)d_in[3];
    float* out = (float*)d_out;

    int E  = in_sizes[2] / 2;   // (E,2) index pairs
    int E4 = E / 4;             // 4-edge chunks
    int tail = E - E4 * 4;
    int S = (E4 + 1) / 2;       // threads; each covers chunks t and t+S

    // 1. zero denom (graph-capturable async memset)
    cudaMemsetAsync(denom_device_addr(), 0, (size_t)MM * sizeof(float));

    // 2. gate table
    dim3 ggrid((RR + 31) / 32, (RR + 31) / 32);
    gemm_sigmoid_kernel<<<ggrid, 256>>>(Gs, Gr);

    // 3. pass 1: gates + segment sum
    int nblk = (S + 255) / 256;
    edge_pass1_kernel<<<nblk, 256>>>(rel4, msg4, (float4*)out, E4, S);
    if (tail) {
        edge_tail_kernel<<<1, 256>>>((const int2*)d_in[2], (const int2*)d_in[3],
                                     out, E4 * 4, E);
    }

    // 4. pass 2: normalize
    edge_pass2_kernel<<<nblk, 256>>>((float4*)out, E4, S);
    if (tail) {
        edge_tail2_kernel<<<1, 256>>>(out, E4 * 4, E);
    }
}

// round 9
// speedup vs baseline: 1.2200x; 1.0439x over previous
#include <cuda_runtime.h>
#include <cuda_bf16.h>

// Problem constants (GatedMessageGcn_3126736191774)
#define RR   1000          // number of relations
#define DD   100           // feature dim
#define MM   2000000       // num_messages (segments)
#define EMAX 16000000      // edges

// ---------------------------------------------------------------------------
// Device scratch (static; no runtime allocation allowed)
// ---------------------------------------------------------------------------
__device__ float g_table[RR * RR];   // sigmoid(Gs @ Gr^T), 4 MB (L2-resident)
__device__ float g_denom[MM];        // segment sums, 8 MB   (L2-resident)
__device__ int   g_recv[EMAX];       // compacted receiver idx, 64 MB

// ---------------------------------------------------------------------------
// Kernel 1: 64x64-tile register-blocked GEMM (K=100) + sigmoid epilogue.
//   256 threads; each computes a 4x4 sub-tile at rows ty+16m, cols tx+16n
//   (strided so the stride-101 smem reads are bank-conflict-free).
//   8 LDS per 16 FMA -> FFMA-issue-bound (~9-12 us predicted).
// ---------------------------------------------------------------------------
#define KPAD 101

__global__ void gemm_sigmoid_kernel(const float* __restrict__ Gs,
                                    const float* __restrict__ Gr) {
    __shared__ float As[64 * KPAD];   // sender rows   [row][k], pad 101
    __shared__ float Bs[64 * KPAD];   // receiver rows [row][k]

    const int tid = threadIdx.x;
    const int i0 = blockIdx.y * 64;
    const int j0 = blockIdx.x * 64;

    // Stage 64 rows x 100 k of each operand (coalesced; conflict-free writes).
    for (int idx = tid; idx < 64 * DD; idx += 256) {
        int row = idx / DD;
        int k   = idx % DD;
        int gi = i0 + row;
        int gj = j0 + row;
        As[row * KPAD + k] = (gi < RR) ? Gs[gi * DD + k] : 0.0f;
        Bs[row * KPAD + k] = (gj < RR) ? Gr[gj * DD + k] : 0.0f;
    }
    __syncthreads();

    const int tx = tid & 15;   // col group
    const int ty = tid >> 4;   // row group

    float acc[4][4];
    #pragma unroll
    for (int m = 0; m < 4; m++)
        #pragma unroll
        for (int n = 0; n < 4; n++) acc[m][n] = 0.0f;

    #pragma unroll 2
    for (int k = 0; k < DD; k++) {
        float a0 = As[(ty     ) * KPAD + k];
        float a1 = As[(ty + 16) * KPAD + k];
        float a2 = As[(ty + 32) * KPAD + k];
        float a3 = As[(ty + 48) * KPAD + k];
        float b0 = Bs[(tx     ) * KPAD + k];
        float b1 = Bs[(tx + 16) * KPAD + k];
        float b2 = Bs[(tx + 32) * KPAD + k];
        float b3 = Bs[(tx + 48) * KPAD + k];

        acc[0][0] += a0 * b0; acc[0][1] += a0 * b1; acc[0][2] += a0 * b2; acc[0][3] += a0 * b3;
        acc[1][0] += a1 * b0; acc[1][1] += a1 * b1; acc[1][2] += a1 * b2; acc[1][3] += a1 * b3;
        acc[2][0] += a2 * b0; acc[2][1] += a2 * b1; acc[2][2] += a2 * b2; acc[2][3] += a2 * b3;
        acc[3][0] += a3 * b0; acc[3][1] += a3 * b1; acc[3][2] += a3 * b2; acc[3][3] += a3 * b3;
    }

    #pragma unroll
    for (int m = 0; m < 4; m++) {
        int i = i0 + ty + 16 * m;
        if (i >= RR) continue;
        #pragma unroll
        for (int n = 0; n < 4; n++) {
            int j = j0 + tx + 16 * n;
            if (j < RR)
                g_table[i * RR + j] = 1.0f / (1.0f + __expf(-acc[m][n]));
        }
    }
}

// ---------------------------------------------------------------------------
// Kernel 2 (pass 1): 4 edges/thread (R4 champion config).
//   4 independent table gathers, coalesced gate/recv stores, 4 REDG atomics.
// ---------------------------------------------------------------------------
__global__ void edge_pass1_kernel(const int4* __restrict__ rel4,
                                  const int4* __restrict__ msg4,
                                  float4* __restrict__ gates4,
                                  int E4) {
    int t = blockIdx.x * blockDim.x + threadIdx.x;
    if (t >= E4) return;

    int4 ra = rel4[2 * t];
    int4 rb = rel4[2 * t + 1];
    int4 ma = msg4[2 * t];
    int4 mb = msg4[2 * t + 1];

    float g0 = __ldg(&g_table[ra.x * RR + ra.y]);
    float g1 = __ldg(&g_table[ra.z * RR + ra.w]);
    float g2 = __ldg(&g_table[rb.x * RR + rb.y]);
    float g3 = __ldg(&g_table[rb.z * RR + rb.w]);

    gates4[t] = make_float4(g0, g1, g2, g3);
    reinterpret_cast<int4*>(g_recv)[t] = make_int4(ma.y, ma.w, mb.y, mb.w);

    atomicAdd(&g_denom[ma.y], g0);   // return unused -> REDG
    atomicAdd(&g_denom[ma.w], g1);
    atomicAdd(&g_denom[mb.y], g2);
    atomicAdd(&g_denom[mb.w], g3);
}

// ---------------------------------------------------------------------------
// Kernel 3 (pass 2): weights = gate / (denom[recv] + 1e-8), 4 edges/thread
// ---------------------------------------------------------------------------
__global__ void edge_pass2_kernel(float4* __restrict__ out4, int E4) {
    int t = blockIdx.x * blockDim.x + threadIdx.x;
    if (t >= E4) return;

    int4   r = reinterpret_cast<const int4*>(g_recv)[t];
    float4 g = out4[t];

    float d0 = __ldg(&g_denom[r.x]);
    float d1 = __ldg(&g_denom[r.y]);
    float d2 = __ldg(&g_denom[r.z]);
    float d3 = __ldg(&g_denom[r.w]);

    out4[t] = make_float4(g.x / (d0 + 1e-8f), g.y / (d1 + 1e-8f),
                          g.z / (d2 + 1e-8f), g.w / (d3 + 1e-8f));
}

// ---------------------------------------------------------------------------
// Scalar tails (E % 4 != 0 safety; E=16M so normally empty)
// ---------------------------------------------------------------------------
__global__ void edge_tail_kernel(const int2* __restrict__ rel,
                                 const int2* __restrict__ msg,
                                 float* __restrict__ gates,
                                 int start, int E) {
    int e = start + blockIdx.x * blockDim.x + threadIdx.x;
    if (e >= E) return;
    int2 rp = rel[e];
    int  rv = msg[e].y;
    float g = __ldg(&g_table[rp.x * RR + rp.y]);
    gates[e] = g;
    g_recv[e] = rv;
    atomicAdd(&g_denom[rv], g);
}

__global__ void edge_tail2_kernel(float* __restrict__ out,
                                  int start, int E) {
    int e = start + blockIdx.x * blockDim.x + threadIdx.x;
    if (e >= E) return;
    out[e] = out[e] / (__ldg(&g_denom[g_recv[e]]) + 1e-8f);
}

// ---------------------------------------------------------------------------
// Host helper: cached symbol address for memset (defined BEFORE use)
// ---------------------------------------------------------------------------
static void* denom_device_addr() {
    static void* p = nullptr;
    if (!p) cudaGetSymbolAddress(&p, g_denom);
    return p;
}

// ---------------------------------------------------------------------------
// Launch
// ---------------------------------------------------------------------------
extern "C" void kernel_launch(void* const* d_in, const int* in_sizes, int n_in,
                              void* d_out, int out_size) {
    const float* Gs = (const float*)d_in[0];
    const float* Gr = (const float*)d_in[1];
    const int4*  rel4 = (const int4*)d_in[2];
    const int4*  msg4 = (const int4*)d_in[3];
    float* out = (float*)d_out;

    int E  = in_sizes[2] / 2;   // (E,2) index pairs
    int E4 = E / 4;
    int tail = E - E4 * 4;

    // 1. zero denom (graph-capturable async memset)
    cudaMemsetAsync(denom_device_addr(), 0, (size_t)MM * sizeof(float));

    // 2. gate table (register-blocked GEMM + sigmoid)
    dim3 ggrid((RR + 63) / 64, (RR + 63) / 64);
    gemm_sigmoid_kernel<<<ggrid, 256>>>(Gs, Gr);

    // 3. pass 1: gates + segment sum
    int nblk = (E4 + 255) / 256;
    edge_pass1_kernel<<<nblk, 256>>>(rel4, msg4, (float4*)out, E4);
    if (tail) {
        edge_tail_kernel<<<1, 256>>>((const int2*)d_in[2], (const int2*)d_in[3],
                                     out, E4 * 4, E);
    }

    // 4. pass 2: normalize
    edge_pass2_kernel<<<nblk, 256>>>((float4*)out, E4);
    if (tail) {
        edge_tail2_kernel<<<1, 256>>>(out, E4 * 4, E);
    }
}